// round 3
// baseline (speedup 1.0000x reference)
#include <cuda_runtime.h>
#include <mma.h>
#include <cstdint>
#include <cstddef>

using namespace nvcuda;

#define T_SEQ 1024
#define B_SZ  64
// E = 256, H = 256, 4H = 1024

// ---------------- device-global scratch (no allocations) ----------------
__device__ float g_x   [(size_t)B_SZ * T_SEQ * 256];   // gathered embeddings
__device__ float g_xw1f[(size_t)B_SZ * T_SEQ * 1024];  // x @ fw1_Wi
__device__ float g_xw1b[(size_t)B_SZ * T_SEQ * 1024];  // x @ bw1_Wi
__device__ float g_xw2 [(size_t)B_SZ * T_SEQ * 1024];  // x1 @ fw2_Wi
__device__ float g_x1  [(size_t)B_SZ * T_SEQ * 512];   // layer-1 output [fwd|bwd]
__device__ float g_hb1f[2 * B_SZ * 256];               // h double buffers
__device__ float g_hb1b[2 * B_SZ * 256];
__device__ float g_hb2 [2 * B_SZ * 256];
__device__ float g_h2f [B_SZ * 256];                   // layer-2 fwd final h
__device__ unsigned g_ctrs[32];                        // group barrier counters

// ---------------- helpers ----------------
__device__ __forceinline__ void fma2(unsigned long long& d,
                                     unsigned long long a,
                                     unsigned long long b) {
    asm("fma.rn.f32x2 %0, %1, %2, %0;" : "+l"(d) : "l"(a), "l"(b));
}
__device__ __forceinline__ float sigf(float x) { return 1.0f / (1.0f + __expf(-x)); }

// ---------------- init: zero h buffers + counters (every replay) ----------------
__global__ void init_kernel() {
    int i = blockIdx.x * blockDim.x + threadIdx.x;
    if (i < 2 * B_SZ * 256) { g_hb1f[i] = 0.f; g_hb1b[i] = 0.f; g_hb2[i] = 0.f; }
    if (i < 32) g_ctrs[i] = 0u;
}

// ---------------- embedding gather ----------------
__global__ void gather_kernel(const int* __restrict__ tok, const float* __restrict__ emb) {
    size_t idx = (size_t)blockIdx.x * blockDim.x + threadIdx.x;  // 65536*64 float4
    int row = (int)(idx >> 6);
    int f   = (int)(idx & 63);
    int t   = __ldg(&tok[row]);
    ((float4*)g_x)[idx] = __ldg(&((const float4*)emb)[(size_t)t * 64 + f]);
}

// ---------------- tf32 WMMA GEMM: C[M,N] = A[M,K] @ B[K,N] ----------------
// CTA 128x128, 8 warps (2x4), warp 64x32, k-chunk 16.
#define LDA 20
#define LDB 132
__global__ __launch_bounds__(256) void gemm_tf32(const float* __restrict__ A,
                                                 const float* __restrict__ B,
                                                 float* __restrict__ C,
                                                 int N, int K) {
    __shared__ float As[128 * LDA];
    __shared__ float Bs[16 * LDB];
    const int tid = threadIdx.x;
    const int w   = tid >> 5;
    const int m0  = blockIdx.y * 128;
    const int n0  = blockIdx.x * 128;
    const int wm0 = (w >> 2) * 64;
    const int wn0 = (w & 3) * 32;

    wmma::fragment<wmma::accumulator, 16, 16, 8, float> c[4][2];
    #pragma unroll
    for (int i = 0; i < 4; i++)
        #pragma unroll
        for (int j = 0; j < 2; j++) wmma::fill_fragment(c[i][j], 0.0f);

    const int nkt = K >> 4;
    for (int kt = 0; kt < nkt; kt++) {
        #pragma unroll
        for (int p = 0; p < 2; p++) {                  // A tile 128x16
            int idx = tid + p * 256;
            int row = idx >> 2, c4 = idx & 3;
            const float4* A4 = (const float4*)(A + (size_t)(m0 + row) * K + kt * 16);
            *(float4*)(As + row * LDA + c4 * 4) = __ldg(&A4[c4]);
        }
        #pragma unroll
        for (int p = 0; p < 2; p++) {                  // B tile 16x128
            int idx = tid + p * 256;
            int row = idx >> 5, c4 = idx & 31;
            const float4* B4 = (const float4*)(B + (size_t)(kt * 16 + row) * N + n0);
            *(float4*)(Bs + row * LDB + c4 * 4) = __ldg(&B4[c4]);
        }
        __syncthreads();
        #pragma unroll
        for (int kk = 0; kk < 16; kk += 8) {
            wmma::fragment<wmma::matrix_a, 16, 16, 8, wmma::precision::tf32, wmma::row_major> a[4];
            wmma::fragment<wmma::matrix_b, 16, 16, 8, wmma::precision::tf32, wmma::row_major> b[2];
            #pragma unroll
            for (int i = 0; i < 4; i++) {
                wmma::load_matrix_sync(a[i], &As[(wm0 + i * 16) * LDA + kk], LDA);
                #pragma unroll
                for (int e = 0; e < a[i].num_elements; e++)
                    a[i].x[e] = wmma::__float_to_tf32(a[i].x[e]);
            }
            #pragma unroll
            for (int j = 0; j < 2; j++) {
                wmma::load_matrix_sync(b[j], &Bs[kk * LDB + wn0 + j * 16], LDB);
                #pragma unroll
                for (int e = 0; e < b[j].num_elements; e++)
                    b[j].x[e] = wmma::__float_to_tf32(b[j].x[e]);
            }
            #pragma unroll
            for (int i = 0; i < 4; i++)
                #pragma unroll
                for (int j = 0; j < 2; j++)
                    wmma::mma_sync(c[i][j], a[i], b[j], c[i][j]);
        }
        __syncthreads();
    }
    #pragma unroll
    for (int i = 0; i < 4; i++)
        #pragma unroll
        for (int j = 0; j < 2; j++)
            wmma::store_matrix_sync(C + (size_t)(m0 + wm0 + i * 16) * N + n0 + wn0 + j * 16,
                                    c[i][j], N, wmma::mem_row_major);
}

// ---------------- persistent LSTM scan ----------------
// Grid: nDir*128 CTAs, 256 threads. CTA (dir, bg, ng): batch rows bg*8..+8,
// h-cols ng*16..+16 (=> 64 z-cols). Wh slice staged once in SMEM.
// smem: Whs[256][64] | hs2[256][20] dup-pair h (aliased by k-split partials) | zb[8*64]
#define SCAN_SMEM ((16384 + 5120 + 512) * 4)
__global__ __launch_bounds__(256, 2) void scan_kernel(
    const float* __restrict__ xw_f, const float* __restrict__ xw_b,
    const float* __restrict__ Wh_f, const float* __restrict__ Wh_b,
    const float* __restrict__ b_f,  const float* __restrict__ b_b,
    float* hb_f, float* hb_b,
    unsigned* ctrs,
    float* x1out, float* h2out) {
    extern __shared__ float sm[];
    float* Whs = sm;              // 16384 floats
    float* hs2 = sm + 16384;      // 5120 floats (also reduction partials)
    float* zb  = sm + 21504;      // 512 floats

    const int tid = threadIdx.x;
    const int dir = blockIdx.x >> 7;
    const int sub = blockIdx.x & 127;
    const int bg  = sub >> 4, ng = sub & 15;
    const int r0  = bg * 8, hc0 = ng * 16;
    const float* xw   = dir ? xw_b : xw_f;
    const float* Whg  = dir ? Wh_b : Wh_f;
    const float* bias = dir ? b_b  : b_f;
    float* hb = dir ? hb_b : hb_f;
    unsigned* ctr = ctrs + (dir * 8 + bg);
    volatile unsigned* vctr = (volatile unsigned*)ctr;

    // stage Wh slice: Whs[k*64 + c], c = gate*16 + j  -> global col gate*256+hc0+j
    for (int i = tid; i < 16384; i += 256) {
        int k = i >> 6, cc = i & 63;
        int gt = cc >> 4, j = cc & 15;
        Whs[i] = __ldg(&Whg[(size_t)k * 1024 + gt * 256 + hc0 + j]);
    }
    // roles
    const int rr = tid >> 5, cp = tid & 31, c0 = cp * 2;   // reduce role (row rr, colpair)
    const int zc0 = ((c0 >> 4) * 256) + hc0 + (c0 & 15);   // global z-col of local col c0
    const float2 bias2 = *(const float2*)(bias + zc0);
    const int gr = tid >> 4, gj = tid & 15;                // gate role (tid<128)
    const int kq = tid >> 5;                               // k-split warp id
    float c_state = 0.0f;
    __syncthreads();

    for (int s = 0; s < T_SEQ; s++) {
        const int t_in = dir ? (T_SEQ - 1 - s) : s;
        // prefetch input projection for this step
        const float2 xwv = __ldcs((const float2*)(xw + ((size_t)(r0 + rr) * T_SEQ + t_in) * 1024 + zc0));
        // load h (parity s&1) from L2; store pair-duplicated: hs2[k*20+2r]=(h,h)
        const float* hread = hb + (s & 1) * (B_SZ * 256);
        #pragma unroll
        for (int it = 0; it < 8; it++) {
            float hv = __ldcg(hread + (r0 + it) * 256 + tid);
            *(float2*)(hs2 + tid * 20 + 2 * it) = make_float2(hv, hv);
        }
        __syncthreads();

        // z partials: warp kq covers k in [kq*32, +32); thread cp: cols (c0,c0+1), 8 rows
        unsigned long long a0 = 0, a1 = 0, a2 = 0, a3 = 0, a4 = 0, a5 = 0, a6 = 0, a7 = 0;
        const int kbase = kq * 32;
        #pragma unroll 4
        for (int kk = 0; kk < 32; kk++) {
            const int k = kbase + kk;
            const ulonglong2* hp = (const ulonglong2*)(hs2 + k * 20);
            ulonglong2 h01 = hp[0], h23 = hp[1], h45 = hp[2], h67 = hp[3];
            unsigned long long wv = *(const unsigned long long*)(Whs + k * 64 + c0);
            fma2(a0, h01.x, wv); fma2(a1, h01.y, wv);
            fma2(a2, h23.x, wv); fma2(a3, h23.y, wv);
            fma2(a4, h45.x, wv); fma2(a5, h45.y, wv);
            fma2(a6, h67.x, wv); fma2(a7, h67.y, wv);
        }
        __syncthreads();
        // partials into smem (alias hs2): part[(row*8 + kq)*32 + cp]
        unsigned long long* part = (unsigned long long*)hs2;
        part[(0 * 8 + kq) * 32 + cp] = a0; part[(1 * 8 + kq) * 32 + cp] = a1;
        part[(2 * 8 + kq) * 32 + cp] = a2; part[(3 * 8 + kq) * 32 + cp] = a3;
        part[(4 * 8 + kq) * 32 + cp] = a4; part[(5 * 8 + kq) * 32 + cp] = a5;
        part[(6 * 8 + kq) * 32 + cp] = a6; part[(7 * 8 + kq) * 32 + cp] = a7;
        __syncthreads();
        // reduce 8 k-splits; thread (rr,cp) -> z[rr][c0..c0+1]
        float2 zv = make_float2(bias2.x + xwv.x, bias2.y + xwv.y);
        const float2* pf = (const float2*)hs2;
        #pragma unroll
        for (int q = 0; q < 8; q++) {
            float2 pv = pf[(rr * 8 + q) * 32 + cp];
            zv.x += pv.x; zv.y += pv.y;
        }
        *(float2*)(zb + rr * 64 + c0) = zv;
        __syncthreads();
        // gates: thread (gr,gj) -> row r0+gr, h-col hc0+gj
        if (tid < 128) {
            float zi = zb[gr * 64 + gj];
            float zf = zb[gr * 64 + 16 + gj];
            float zg = zb[gr * 64 + 32 + gj];
            float zo = zb[gr * 64 + 48 + gj];
            c_state = sigf(zf) * c_state + sigf(zi) * tanhf(zg);
            float hval = sigf(zo) * tanhf(c_state);
            __stcg(hb + ((s + 1) & 1) * (B_SZ * 256) + (r0 + gr) * 256 + hc0 + gj, hval);
            if (x1out)
                __stcg(x1out + ((size_t)(r0 + gr) * T_SEQ + t_in) * 512 + dir * 256 + hc0 + gj, hval);
            if (h2out && s == T_SEQ - 1)
                h2out[(r0 + gr) * 256 + hc0 + gj] = hval;
        }
        if (s == T_SEQ - 1) break;
        __threadfence();
        __syncthreads();
        if (tid == 0) {
            atomicAdd(ctr, 1u);
            const unsigned tgt = 16u * (unsigned)(s + 1);
            while (*vctr < tgt) { }
        }
        __threadfence();
        __syncthreads();
    }
}

// ---------------- head: layer-2 bwd single step + final dot + sigmoid ----------------
__global__ __launch_bounds__(256) void head_kernel(const float* __restrict__ Wi,
                                                   const float* __restrict__ b2,
                                                   const float* __restrict__ Wd,
                                                   const float* __restrict__ bd,
                                                   float* __restrict__ out) {
    __shared__ float xr[512];
    __shared__ float z[1024];
    __shared__ float red[8];
    const int b = blockIdx.x, tid = threadIdx.x;
    const float* xrow = g_x1 + ((size_t)b * T_SEQ + (T_SEQ - 1)) * 512;
    xr[tid] = xrow[tid];
    xr[tid + 256] = xrow[tid + 256];
    __syncthreads();
    const int c0 = tid * 4;
    float4 acc = *(const float4*)(b2 + c0);
    for (int k = 0; k < 512; k++) {
        float xv = xr[k];
        float4 wv = __ldg((const float4*)(Wi + (size_t)k * 1024 + c0));
        acc.x = fmaf(xv, wv.x, acc.x);
        acc.y = fmaf(xv, wv.y, acc.y);
        acc.z = fmaf(xv, wv.z, acc.z);
        acc.w = fmaf(xv, wv.w, acc.w);
    }
    *(float4*)(z + c0) = acc;
    __syncthreads();
    float zi = z[tid], zg = z[512 + tid], zo = z[768 + tid];
    float cst = sigf(zi) * tanhf(zg);           // c0 = 0 so forget term vanishes
    float h2b = sigf(zo) * tanhf(cst);
    float pl = g_h2f[b * 256 + tid] * __ldg(&Wd[tid]) + h2b * __ldg(&Wd[256 + tid]);
    #pragma unroll
    for (int off = 16; off; off >>= 1) pl += __shfl_down_sync(0xffffffffu, pl, off);
    if ((tid & 31) == 0) red[tid >> 5] = pl;
    __syncthreads();
    if (tid == 0) {
        float ssum = 0.f;
        #pragma unroll
        for (int q = 0; q < 8; q++) ssum += red[q];
        out[b] = sigf(ssum + bd[0]);
    }
}

// ---------------- launch ----------------
extern "C" void kernel_launch(void* const* d_in, const int* in_sizes, int n_in,
                              void* d_out, int out_size) {
    const int*   tokens = (const int*)  d_in[0];
    const float* embed  = (const float*)d_in[1];
    const float* fw1_Wi = (const float*)d_in[2];
    const float* fw1_Wh = (const float*)d_in[3];
    const float* fw1_b  = (const float*)d_in[4];
    const float* bw1_Wi = (const float*)d_in[5];
    const float* bw1_Wh = (const float*)d_in[6];
    const float* bw1_b  = (const float*)d_in[7];
    const float* fw2_Wi = (const float*)d_in[8];
    const float* fw2_Wh = (const float*)d_in[9];
    const float* fw2_b  = (const float*)d_in[10];
    const float* bw2_Wi = (const float*)d_in[11];
    const float* bw2_b  = (const float*)d_in[13];
    const float* Wd     = (const float*)d_in[14];
    const float* bd     = (const float*)d_in[15];
    float* out = (float*)d_out;

    float *px, *pxw1f, *pxw1b, *pxw2, *px1, *phb1f, *phb1b, *phb2, *ph2f;
    unsigned* pctrs;
    cudaGetSymbolAddress((void**)&px,    g_x);
    cudaGetSymbolAddress((void**)&pxw1f, g_xw1f);
    cudaGetSymbolAddress((void**)&pxw1b, g_xw1b);
    cudaGetSymbolAddress((void**)&pxw2,  g_xw2);
    cudaGetSymbolAddress((void**)&px1,   g_x1);
    cudaGetSymbolAddress((void**)&phb1f, g_hb1f);
    cudaGetSymbolAddress((void**)&phb1b, g_hb1b);
    cudaGetSymbolAddress((void**)&phb2,  g_hb2);
    cudaGetSymbolAddress((void**)&ph2f,  g_h2f);
    cudaGetSymbolAddress((void**)&pctrs, g_ctrs);

    cudaFuncSetAttribute(scan_kernel, cudaFuncAttributeMaxDynamicSharedMemorySize, SCAN_SMEM);

    init_kernel<<<128, 256>>>();
    gather_kernel<<<16384, 256>>>(tokens, embed);
    gemm_tf32<<<dim3(8, 512), 256>>>(px, fw1_Wi, pxw1f, 1024, 256);
    gemm_tf32<<<dim3(8, 512), 256>>>(px, bw1_Wi, pxw1b, 1024, 256);
    scan_kernel<<<256, 256, SCAN_SMEM>>>(pxw1f, pxw1b, fw1_Wh, bw1_Wh, fw1_b, bw1_b,
                                         phb1f, phb1b, pctrs, px1, nullptr);
    gemm_tf32<<<dim3(8, 512), 256>>>(px1, fw2_Wi, pxw2, 1024, 512);
    scan_kernel<<<128, 256, SCAN_SMEM>>>(pxw2, pxw2, fw2_Wh, fw2_Wh, fw2_b, fw2_b,
                                         phb2, phb2, pctrs + 16, nullptr, ph2f);
    head_kernel<<<64, 256>>>(bw2_Wi, bw2_b, Wd, bd, out);
}

// round 4
// speedup vs baseline: 1.4879x; 1.4879x over previous
#include <cuda_runtime.h>
#include <cuda_bf16.h>
#include <mma.h>
#include <cstdint>
#include <cstddef>

using namespace nvcuda;

#define T_SEQ 1024
#define B_SZ  64
// E = 256, H = 256, 4H = 1024

// ---------------- device-global scratch (no allocations) ----------------
__device__ float g_x   [(size_t)B_SZ * T_SEQ * 256];   // gathered embeddings
__device__ float g_xw1f[(size_t)B_SZ * T_SEQ * 1024];  // x @ fw1_Wi
__device__ float g_xw1b[(size_t)B_SZ * T_SEQ * 1024];  // x @ bw1_Wi
__device__ float g_xw2 [(size_t)B_SZ * T_SEQ * 1024];  // x1 @ fw2_Wi
__device__ float g_x1  [(size_t)B_SZ * T_SEQ * 512];   // layer-1 output [fwd|bwd]
__device__ __nv_bfloat16 g_hb1f[2 * B_SZ * 256];       // h double buffers (bf16)
__device__ __nv_bfloat16 g_hb1b[2 * B_SZ * 256];
__device__ __nv_bfloat16 g_hb2 [2 * B_SZ * 256];
__device__ float g_h2f [B_SZ * 256];                   // layer-2 fwd final h
__device__ unsigned g_ctrs[32];                        // group barrier counters

// ---------------- helpers ----------------
__device__ __forceinline__ float sigf(float x) {
    return __fdividef(1.0f, 1.0f + __expf(-x));
}
__device__ __forceinline__ float tanhfast(float x) {
    // tanh(x) = 1 - 2/(e^{2x}+1); saturates correctly at +-inf
    float e = __expf(2.0f * x);
    return 1.0f - __fdividef(2.0f, e + 1.0f);
}

// ---------------- init: zero h buffers + counters (every replay) ----------------
__global__ void init_kernel() {
    int i = blockIdx.x * blockDim.x + threadIdx.x;
    if (i < 2 * B_SZ * 256) {
        g_hb1f[i] = __float2bfloat16(0.f);
        g_hb1b[i] = __float2bfloat16(0.f);
        g_hb2[i]  = __float2bfloat16(0.f);
    }
    if (i < 32) g_ctrs[i] = 0u;
}

// ---------------- embedding gather ----------------
__global__ void gather_kernel(const int* __restrict__ tok, const float* __restrict__ emb) {
    size_t idx = (size_t)blockIdx.x * blockDim.x + threadIdx.x;  // 65536*64 float4
    int row = (int)(idx >> 6);
    int f   = (int)(idx & 63);
    int t   = __ldg(&tok[row]);
    ((float4*)g_x)[idx] = __ldg(&((const float4*)emb)[(size_t)t * 64 + f]);
}

// ---------------- tf32 WMMA GEMM: C[M,N] = A[M,K] @ B[K,N] ----------------
#define LDA 20
#define LDB 132
__global__ __launch_bounds__(256) void gemm_tf32(const float* __restrict__ A,
                                                 const float* __restrict__ B,
                                                 float* __restrict__ C,
                                                 int N, int K) {
    __shared__ float As[128 * LDA];
    __shared__ float Bs[16 * LDB];
    const int tid = threadIdx.x;
    const int w   = tid >> 5;
    const int m0  = blockIdx.y * 128;
    const int n0  = blockIdx.x * 128;
    const int wm0 = (w >> 2) * 64;
    const int wn0 = (w & 3) * 32;

    wmma::fragment<wmma::accumulator, 16, 16, 8, float> c[4][2];
    #pragma unroll
    for (int i = 0; i < 4; i++)
        #pragma unroll
        for (int j = 0; j < 2; j++) wmma::fill_fragment(c[i][j], 0.0f);

    const int nkt = K >> 4;
    for (int kt = 0; kt < nkt; kt++) {
        #pragma unroll
        for (int p = 0; p < 2; p++) {                  // A tile 128x16
            int idx = tid + p * 256;
            int row = idx >> 2, c4 = idx & 3;
            const float4* A4 = (const float4*)(A + (size_t)(m0 + row) * K + kt * 16);
            *(float4*)(As + row * LDA + c4 * 4) = __ldg(&A4[c4]);
        }
        #pragma unroll
        for (int p = 0; p < 2; p++) {                  // B tile 16x128
            int idx = tid + p * 256;
            int row = idx >> 5, c4 = idx & 31;
            const float4* B4 = (const float4*)(B + (size_t)(kt * 16 + row) * N + n0);
            *(float4*)(Bs + row * LDB + c4 * 4) = __ldg(&B4[c4]);
        }
        __syncthreads();
        #pragma unroll
        for (int kk = 0; kk < 16; kk += 8) {
            wmma::fragment<wmma::matrix_a, 16, 16, 8, wmma::precision::tf32, wmma::row_major> a[4];
            wmma::fragment<wmma::matrix_b, 16, 16, 8, wmma::precision::tf32, wmma::row_major> b[2];
            #pragma unroll
            for (int i = 0; i < 4; i++) {
                wmma::load_matrix_sync(a[i], &As[(wm0 + i * 16) * LDA + kk], LDA);
                #pragma unroll
                for (int e = 0; e < a[i].num_elements; e++)
                    a[i].x[e] = wmma::__float_to_tf32(a[i].x[e]);
            }
            #pragma unroll
            for (int j = 0; j < 2; j++) {
                wmma::load_matrix_sync(b[j], &Bs[kk * LDB + wn0 + j * 16], LDB);
                #pragma unroll
                for (int e = 0; e < b[j].num_elements; e++)
                    b[j].x[e] = wmma::__float_to_tf32(b[j].x[e]);
            }
            #pragma unroll
            for (int i = 0; i < 4; i++)
                #pragma unroll
                for (int j = 0; j < 2; j++)
                    wmma::mma_sync(c[i][j], a[i], b[j], c[i][j]);
        }
        __syncthreads();
    }
    #pragma unroll
    for (int i = 0; i < 4; i++)
        #pragma unroll
        for (int j = 0; j < 2; j++)
            wmma::store_matrix_sync(C + (size_t)(m0 + wm0 + i * 16) * N + n0 + wn0 + j * 16,
                                    c[i][j], N, wmma::mem_row_major);
}

// ---------------- persistent LSTM scan (bf16 tensor-core recurrence) ----------------
// Grid: nDir*128 CTAs, 256 threads. CTA (dir, bg, ng): batch rows bg*8..+8,
// h-cols ng*16..+16 (=> 64 local z-cols, c = gate*16 + j).
// SMEM (dynamic): Whs bf16 [256][72] | hs bf16 [16][264] (rows 8..15 = 0) | zb f32 [16][68]
#define WHS_LD 72
#define HS_LD  264
#define ZB_LD  68
#define WHS_BYTES (256 * WHS_LD * 2)          // 36864
#define HS_OFF    WHS_BYTES
#define HS_BYTES  (16 * HS_LD * 2)            // 8448
#define ZB_OFF    (HS_OFF + HS_BYTES)         // 45312
#define ZB_BYTES  (16 * ZB_LD * 4)            // 4352
#define SCAN_SMEM (ZB_OFF + ZB_BYTES)         // 49664

__global__ __launch_bounds__(256, 2) void scan_kernel(
    const float* __restrict__ xw_f, const float* __restrict__ xw_b,
    const float* __restrict__ Wh_f, const float* __restrict__ Wh_b,
    const float* __restrict__ b_f,  const float* __restrict__ b_b,
    __nv_bfloat16* hb_f, __nv_bfloat16* hb_b,
    unsigned* ctrs,
    float* x1out, float* h2out) {
    extern __shared__ char sm[];
    __nv_bfloat16* Whs = (__nv_bfloat16*)sm;
    __nv_bfloat16* hs  = (__nv_bfloat16*)(sm + HS_OFF);
    float*         zb  = (float*)(sm + ZB_OFF);

    const int tid = threadIdx.x;
    const int w   = tid >> 5;
    const int dir = blockIdx.x >> 7;
    const int sub = blockIdx.x & 127;
    const int bg  = sub >> 4, ng = sub & 15;
    const int r0  = bg * 8, hc0 = ng * 16;
    const float* xw   = dir ? xw_b : xw_f;
    const float* Whg  = dir ? Wh_b : Wh_f;
    const float* bias = dir ? b_b  : b_f;
    __nv_bfloat16* hb = dir ? hb_b : hb_f;
    unsigned* ctr = ctrs + (dir * 8 + bg);

    // zero hs (rows 8..15 stay zero forever -> M padded to 16)
    for (int i = tid; i < 16 * HS_LD; i += 256) hs[i] = __float2bfloat16(0.f);
    // stage Wh slice as bf16: Whs[k][c], c = gate*16+j -> global col gate*256+hc0+j
    for (int i = tid; i < 256 * 64; i += 256) {
        int k = i >> 6, cc = i & 63;
        int gt = cc >> 4, j = cc & 15;
        Whs[k * WHS_LD + cc] = __float2bfloat16_rn(__ldg(&Whg[(size_t)k * 1024 + gt * 256 + hc0 + j]));
    }

    // h-load role: row = tid>>5 (8 rows), 8 bf16 (16B) per thread
    const int lrow = tid >> 5;
    const int lcol = (tid & 31) * 8;
    // gate role (tid < 128): row gr, h-col gj
    const int gr = tid >> 4, gj = tid & 15;
    const int xwbase = hc0 + gj;
    float bi = 0.f, bfv = 0.f, bgv = 0.f, bo = 0.f;
    if (tid < 128) {
        bi  = __ldg(&bias[0 * 256 + xwbase]);
        bfv = __ldg(&bias[1 * 256 + xwbase]);
        bgv = __ldg(&bias[2 * 256 + xwbase]);
        bo  = __ldg(&bias[3 * 256 + xwbase]);
    }
    float c_state = 0.0f;
    __syncthreads();

    // prefetch xw for step 0
    float xwi = 0.f, xwf = 0.f, xwg = 0.f, xwo = 0.f;
    if (tid < 128) {
        int t0 = dir ? (T_SEQ - 1) : 0;
        const float* p = xw + ((size_t)(r0 + gr) * T_SEQ + t0) * 1024 + xwbase;
        xwi = __ldcs(p); xwf = __ldcs(p + 256); xwg = __ldcs(p + 512); xwo = __ldcs(p + 768);
    }

    for (int s = 0; s < T_SEQ; s++) {
        const int t_in = dir ? (T_SEQ - 1 - s) : s;
        // load h (parity s&1) from L2 as bf16 into hs rows 0..7
        {
            const __nv_bfloat16* hread = hb + (s & 1) * (B_SZ * 256) + (r0 + lrow) * 256 + lcol;
            uint4 hv = __ldcg((const uint4*)hread);
            *(uint4*)(hs + lrow * HS_LD + lcol) = hv;
        }
        __syncthreads();

        // tensor-core z: warps 4..7, warp (w-4) owns local cols n0..n0+15
        if (w >= 4) {
            const int n0 = (w - 4) * 16;
            wmma::fragment<wmma::accumulator, 16, 16, 16, float> acc0, acc1;
            wmma::fill_fragment(acc0, 0.0f);
            wmma::fill_fragment(acc1, 0.0f);
            #pragma unroll
            for (int kk = 0; kk < 16; kk += 2) {
                wmma::fragment<wmma::matrix_a, 16, 16, 16, __nv_bfloat16, wmma::row_major> a0, a1;
                wmma::fragment<wmma::matrix_b, 16, 16, 16, __nv_bfloat16, wmma::row_major> bb0, bb1;
                wmma::load_matrix_sync(a0, hs + kk * 16, HS_LD);
                wmma::load_matrix_sync(bb0, Whs + (kk * 16) * WHS_LD + n0, WHS_LD);
                wmma::mma_sync(acc0, a0, bb0, acc0);
                wmma::load_matrix_sync(a1, hs + (kk + 1) * 16, HS_LD);
                wmma::load_matrix_sync(bb1, Whs + ((kk + 1) * 16) * WHS_LD + n0, WHS_LD);
                wmma::mma_sync(acc1, a1, bb1, acc1);
            }
            #pragma unroll
            for (int e = 0; e < acc0.num_elements; e++) acc0.x[e] += acc1.x[e];
            wmma::store_matrix_sync(zb + n0, acc0, ZB_LD, wmma::mem_row_major);
        }
        __syncthreads();

        // gates
        if (tid < 128) {
            float zi = zb[gr * ZB_LD +      gj] + bi  + xwi;
            float zf = zb[gr * ZB_LD + 16 + gj] + bfv + xwf;
            float zg = zb[gr * ZB_LD + 32 + gj] + bgv + xwg;
            float zo = zb[gr * ZB_LD + 48 + gj] + bo  + xwo;
            c_state = sigf(zf) * c_state + sigf(zi) * tanhfast(zg);
            float hval = sigf(zo) * tanhfast(c_state);
            hb[((s + 1) & 1) * (B_SZ * 256) + (r0 + gr) * 256 + hc0 + gj] = __float2bfloat16_rn(hval);
            if (x1out)
                __stcg(x1out + ((size_t)(r0 + gr) * T_SEQ + t_in) * 512 + dir * 256 + hc0 + gj, hval);
            if (h2out && s == T_SEQ - 1)
                h2out[(r0 + gr) * 256 + hc0 + gj] = hval;
            // prefetch xw for next step (hides DRAM latency behind barrier+mma)
            if (s + 1 < T_SEQ) {
                int tn = dir ? (T_SEQ - 2 - s) : (s + 1);
                const float* p = xw + ((size_t)(r0 + gr) * T_SEQ + tn) * 1024 + xwbase;
                xwi = __ldcs(p); xwf = __ldcs(p + 256); xwg = __ldcs(p + 512); xwo = __ldcs(p + 768);
            }
        }
        if (s == T_SEQ - 1) break;

        // group barrier: release-arrive + acquire-poll (no MEMBAR.GPU)
        __syncthreads();
        if (tid == 0) {
            asm volatile("red.release.gpu.global.add.u32 [%0], %1;" :: "l"(ctr), "r"(1u) : "memory");
            const unsigned tgt = 16u * (unsigned)(s + 1);
            unsigned v;
            do {
                asm volatile("ld.acquire.gpu.global.u32 %0, [%1];" : "=r"(v) : "l"(ctr) : "memory");
            } while (v < tgt);
        }
        __syncthreads();
    }
}

// ---------------- head: layer-2 bwd single step + final dot + sigmoid ----------------
__global__ __launch_bounds__(256) void head_kernel(const float* __restrict__ Wi,
                                                   const float* __restrict__ b2,
                                                   const float* __restrict__ Wd,
                                                   const float* __restrict__ bd,
                                                   float* __restrict__ out) {
    __shared__ float xr[512];
    __shared__ float z[1024];
    __shared__ float red[8];
    const int b = blockIdx.x, tid = threadIdx.x;
    const float* xrow = g_x1 + ((size_t)b * T_SEQ + (T_SEQ - 1)) * 512;
    xr[tid] = xrow[tid];
    xr[tid + 256] = xrow[tid + 256];
    __syncthreads();
    const int c0 = tid * 4;
    float4 acc = *(const float4*)(b2 + c0);
    for (int k = 0; k < 512; k++) {
        float xv = xr[k];
        float4 wv = __ldg((const float4*)(Wi + (size_t)k * 1024 + c0));
        acc.x = fmaf(xv, wv.x, acc.x);
        acc.y = fmaf(xv, wv.y, acc.y);
        acc.z = fmaf(xv, wv.z, acc.z);
        acc.w = fmaf(xv, wv.w, acc.w);
    }
    *(float4*)(z + c0) = acc;
    __syncthreads();
    float zi = z[tid], zg = z[512 + tid], zo = z[768 + tid];
    float cst = sigf(zi) * tanhf(zg);           // c0 = 0 so forget term vanishes
    float h2b = sigf(zo) * tanhf(cst);
    float pl = g_h2f[b * 256 + tid] * __ldg(&Wd[tid]) + h2b * __ldg(&Wd[256 + tid]);
    #pragma unroll
    for (int off = 16; off; off >>= 1) pl += __shfl_down_sync(0xffffffffu, pl, off);
    if ((tid & 31) == 0) red[tid >> 5] = pl;
    __syncthreads();
    if (tid == 0) {
        float ssum = 0.f;
        #pragma unroll
        for (int q = 0; q < 8; q++) ssum += red[q];
        out[b] = sigf(ssum + bd[0]);
    }
}

// ---------------- launch ----------------
extern "C" void kernel_launch(void* const* d_in, const int* in_sizes, int n_in,
                              void* d_out, int out_size) {
    const int*   tokens = (const int*)  d_in[0];
    const float* embed  = (const float*)d_in[1];
    const float* fw1_Wi = (const float*)d_in[2];
    const float* fw1_Wh = (const float*)d_in[3];
    const float* fw1_b  = (const float*)d_in[4];
    const float* bw1_Wi = (const float*)d_in[5];
    const float* bw1_Wh = (const float*)d_in[6];
    const float* bw1_b  = (const float*)d_in[7];
    const float* fw2_Wi = (const float*)d_in[8];
    const float* fw2_Wh = (const float*)d_in[9];
    const float* fw2_b  = (const float*)d_in[10];
    const float* bw2_Wi = (const float*)d_in[11];
    const float* bw2_b  = (const float*)d_in[13];
    const float* Wd     = (const float*)d_in[14];
    const float* bd     = (const float*)d_in[15];
    float* out = (float*)d_out;

    float *px, *pxw1f, *pxw1b, *pxw2, *px1, *ph2f;
    __nv_bfloat16 *phb1f, *phb1b, *phb2;
    unsigned* pctrs;
    cudaGetSymbolAddress((void**)&px,    g_x);
    cudaGetSymbolAddress((void**)&pxw1f, g_xw1f);
    cudaGetSymbolAddress((void**)&pxw1b, g_xw1b);
    cudaGetSymbolAddress((void**)&pxw2,  g_xw2);
    cudaGetSymbolAddress((void**)&px1,   g_x1);
    cudaGetSymbolAddress((void**)&phb1f, g_hb1f);
    cudaGetSymbolAddress((void**)&phb1b, g_hb1b);
    cudaGetSymbolAddress((void**)&phb2,  g_hb2);
    cudaGetSymbolAddress((void**)&ph2f,  g_h2f);
    cudaGetSymbolAddress((void**)&pctrs, g_ctrs);

    cudaFuncSetAttribute(scan_kernel, cudaFuncAttributeMaxDynamicSharedMemorySize, SCAN_SMEM);

    init_kernel<<<128, 256>>>();
    gather_kernel<<<16384, 256>>>(tokens, embed);
    gemm_tf32<<<dim3(8, 512), 256>>>(px, fw1_Wi, pxw1f, 1024, 256);
    gemm_tf32<<<dim3(8, 512), 256>>>(px, bw1_Wi, pxw1b, 1024, 256);
    scan_kernel<<<256, 256, SCAN_SMEM>>>(pxw1f, pxw1b, fw1_Wh, bw1_Wh, fw1_b, bw1_b,
                                         phb1f, phb1b, pctrs, px1, nullptr);
    gemm_tf32<<<dim3(8, 512), 256>>>(px1, fw2_Wi, pxw2, 1024, 512);
    scan_kernel<<<128, 256, SCAN_SMEM>>>(pxw2, pxw2, fw2_Wh, fw2_Wh, fw2_b, fw2_b,
                                         phb2, phb2, pctrs + 16, nullptr, ph2f);
    head_kernel<<<64, 256>>>(bw2_Wi, bw2_b, Wd, bd, out);
}